// round 12
// baseline (speedup 1.0000x reference)
#include <cuda_runtime.h>
#include <cuda_bf16.h>
#include <math.h>
#include <stdint.h>

#define D_NODE 256
#define D_IN   128
#define HID    256
#define EAF    16
#define MAXN   65536

// single dynamic-shared declaration for all kernels
extern __shared__ unsigned char dynsmem[];

// ---------------- device globals (no cudaMalloc allowed) --------------------
__device__ float g_hnode[(size_t)MAXN * D_IN];                  // 32 MB
// 145 weight chunk images (k=16): hi 256x24 halves (48B rows) + lo -> 24576 B each
__device__ __align__(128) unsigned char g_Bimg[145 * 24576];    // ~3.6 MB
__device__ int g_is64;

// ---------------- helpers ----------------------------------------------------
__device__ __forceinline__ float lrelu(float v) { return v >= 0.f ? v : 0.01f * v; }
__device__ __forceinline__ unsigned long long pack2(float a) {
    unsigned long long r; asm("mov.b64 %0, {%1, %1};" : "=l"(r) : "f"(a)); return r;
}
__device__ __forceinline__ void fma2(unsigned long long& d,
                                     unsigned long long a, unsigned long long b) {
    asm("fma.rn.f32x2 %0, %1, %2, %0;" : "+l"(d) : "l"(a), "l"(b));
}
__device__ __forceinline__ float2 unpack2(unsigned long long v) {
    float2 r; asm("mov.b64 {%0, %1}, %2;" : "=f"(r.x), "=f"(r.y) : "l"(v)); return r;
}
__device__ __forceinline__ uint32_t smem_u32(const void* p) {
    uint32_t a; asm("{ .reg .u64 t; cvta.to.shared.u64 t, %1; cvt.u32.u64 %0, t; }" : "=r"(a) : "l"(p));
    return a;
}
__device__ __forceinline__ void mbar_init(uint32_t a, uint32_t cnt) {
    asm volatile("mbarrier.init.shared.b64 [%0], %1;" :: "r"(a), "r"(cnt) : "memory");
}
__device__ __forceinline__ void mbar_arrive(uint32_t a) {
    asm volatile("mbarrier.arrive.shared.b64 _, [%0];" :: "r"(a) : "memory");
}
__device__ __forceinline__ void mbar_expect_tx(uint32_t a, uint32_t tx) {
    asm volatile("mbarrier.arrive.expect_tx.shared.b64 _, [%0], %1;" :: "r"(a), "r"(tx) : "memory");
}
__device__ __forceinline__ void mbar_wait(uint32_t a, uint32_t parity) {
    asm volatile("{\n\t.reg .pred P;\n\tLW%=:\n\t"
                 "mbarrier.try_wait.parity.shared::cta.b64 P, [%0], %1, 0x989680;\n\t"
                 "@!P bra LW%=;\n\t}" :: "r"(a), "r"(parity) : "memory");
}
__device__ __forceinline__ void bulk_copy(uint32_t dst, uint64_t gsrc, uint32_t bytes, uint32_t mbar) {
    asm volatile("cp.async.bulk.shared::cluster.global.mbarrier::complete_tx::bytes [%0], [%1], %2, [%3];"
                 :: "r"(dst), "l"(gsrc), "r"(bytes), "r"(mbar) : "memory");
}
// bf16 HMMA: D[16x8] += A[16x16] * B[16x8]  (row.col, f32 acc)
__device__ __forceinline__ void mma16816(float* c, const uint32_t* a, const uint32_t* b) {
    asm volatile("mma.sync.aligned.m16n8k16.row.col.f32.bf16.bf16.f32 "
                 "{%0,%1,%2,%3}, {%4,%5,%6,%7}, {%8,%9}, {%0,%1,%2,%3};"
                 : "+f"(c[0]), "+f"(c[1]), "+f"(c[2]), "+f"(c[3])
                 : "r"(a[0]), "r"(a[1]), "r"(a[2]), "r"(a[3]), "r"(b[0]), "r"(b[1]));
}
#define LDM4(r, addr) \
    asm volatile("ldmatrix.sync.aligned.m8n8.x4.shared.b16 {%0,%1,%2,%3}, [%4];" \
                 : "=r"((r)[0]), "=r"((r)[1]), "=r"((r)[2]), "=r"((r)[3]) : "r"(addr))

__device__ __forceinline__ uint32_t bsplit2(float v0, float v1, uint32_t& lo_out) {
    __nv_bfloat16 h0 = __float2bfloat16(v0), h1 = __float2bfloat16(v1);
    float r0 = v0 - __bfloat162float(h0), r1 = v1 - __bfloat162float(h1);
    __nv_bfloat16 l0 = __float2bfloat16(r0), l1 = __float2bfloat16(r1);
    lo_out = (uint32_t)__bfloat16_as_ushort(l0) | ((uint32_t)__bfloat16_as_ushort(l1) << 16);
    return (uint32_t)__bfloat16_as_ushort(h0) | ((uint32_t)__bfloat16_as_ushort(h1) << 16);
}

// ---------------- index dtype detection -------------------------------------
__global__ void detect_idx64_kernel(const int* __restrict__ ei) {
    if (threadIdx.x == 0) {
        int allzero = 1;
        for (int i = 1; i < 256; i += 2)
            if (ei[i] != 0) { allzero = 0; break; }
        g_is64 = allzero;
    }
}

// ---------------- weight prep -------------------------------------------------
// 145 chunks of k=16: chunks 0..16 -> W0 (K=272 = 17*16); 17..144 -> W_mid.
// Image: W^T halves at [n][k], row stride 24 halves (48 B, LDSM conflict-free);
// hi at 0, lo at +12288. Chunk stride 24576 B.
__global__ void prep_w_kernel(const float* __restrict__ W0, const float* __restrict__ Wm) {
    int b = blockIdx.x;            // 145 * 256 blocks
    int chunk = b >> 8;
    int n     = b & 255;
    int t     = threadIdx.x;       // 8 threads, one k-pair each
    int k0 = 2 * t;
    float w0, w1;
    if (chunk < 17) {
        int kg = chunk * 16 + k0;
        w0 = W0[(size_t)kg       * HID + n];
        w1 = W0[(size_t)(kg + 1) * HID + n];
    } else {
        int l = (chunk - 17) >> 4, kg = ((chunk - 17) & 15) * 16 + k0;
        const float* W = Wm + (size_t)l * HID * HID + (size_t)kg * HID + n;
        w0 = W[0]; w1 = W[HID];
    }
    uint32_t lo, hi = bsplit2(w0, w1, lo);
    unsigned char* img = g_Bimg + (size_t)chunk * 24576;
    *(uint32_t*)(img + n * 48 + k0 * 2)         = hi;
    *(uint32_t*)(img + 12288 + n * 48 + k0 * 2) = lo;
}

// ---------------- node MLP (fp32 FFMA2, proven) ------------------------------
#define NODE_SMEM ((64 * 260 + 16 * 128) * 4)
__global__ __launch_bounds__(256, 1)
void node_mlp_kernel(const float* __restrict__ x, const float* __restrict__ Wx,
                     const float* __restrict__ bx, int N)
{
    float* smem = (float*)dynsmem;
    float* sX = smem;
    float* sW = smem + 64 * 260;
    const int tid = threadIdx.x;
    const int tx = tid & 15, ty = tid >> 4;
    const int m0 = blockIdx.x * 64;
    {
        int e = tid >> 2, p = tid & 3;
        int r = m0 + e; if (r >= N) r = N - 1;
        const float4* src = (const float4*)(x + (size_t)r * D_NODE) + p * 16;
        float4* dst = (float4*)(sX + e * 260) + p * 16;
        #pragma unroll
        for (int j = 0; j < 16; j++) dst[j] = src[j];
    }
    const int krow = tid >> 4, seg = tid & 15;
    const float4* gsrc = (const float4*)(Wx + krow * D_IN + seg * 8);
    float4 p0 = gsrc[0], p1 = gsrc[1];
    unsigned long long acc[4][4];
    #pragma unroll
    for (int i = 0; i < 4; i++)
        #pragma unroll
        for (int j = 0; j < 4; j++) acc[i][j] = 0ull;
    const float* aBase = sX + (ty * 4) * 260;
    #pragma unroll 1
    for (int c = 0; c < 16; c++) {
        __syncthreads();
        float4* wd = (float4*)(sW + krow * D_IN + seg * 8);
        wd[0] = p0; wd[1] = p1;
        __syncthreads();
        if (c < 15) { const float4* g2 = gsrc + (size_t)(c + 1) * 512; p0 = g2[0]; p1 = g2[1]; }
        const float* aP = aBase + c * 16;
        #pragma unroll
        for (int kk = 0; kk < 16; kk++) {
            unsigned long long a0 = pack2(aP[kk]);
            unsigned long long a1 = pack2(aP[260 + kk]);
            unsigned long long a2 = pack2(aP[520 + kk]);
            unsigned long long a3 = pack2(aP[780 + kk]);
            const float* wrow = sW + kk * D_IN + tx * 4;
            #pragma unroll
            for (int g = 0; g < 2; g++) {
                ulonglong2 w = *(const ulonglong2*)(wrow + g * 64);
                fma2(acc[0][2*g], a0, w.x); fma2(acc[0][2*g+1], a0, w.y);
                fma2(acc[1][2*g], a1, w.x); fma2(acc[1][2*g+1], a1, w.y);
                fma2(acc[2][2*g], a2, w.x); fma2(acc[2][2*g+1], a2, w.y);
                fma2(acc[3][2*g], a3, w.x); fma2(acc[3][2*g+1], a3, w.y);
            }
        }
    }
    #pragma unroll
    for (int g = 0; g < 2; g++) {
        float4 bias = *(const float4*)(bx + tx * 4 + g * 64);
        #pragma unroll
        for (int i = 0; i < 4; i++) {
            int r = m0 + ty * 4 + i;
            if (r < N) {
                float2 u0 = unpack2(acc[i][2*g]);
                float2 u1 = unpack2(acc[i][2*g+1]);
                float4 v = make_float4(lrelu(u0.x + bias.x), lrelu(u0.y + bias.y),
                                       lrelu(u1.x + bias.z), lrelu(u1.y + bias.w));
                *(float4*)(g_hnode + (size_t)r * D_IN + tx * 4 + g * 64) = v;
            }
        }
    }
}

// ---------------- fused mma.sync edge pipeline (M=128, ldmatrix) --------------
// SMEM layout (bytes):
//   sAh  : 0       (128 x 296 halves = 75776)
//   sAl  : 75776   (75776)
//   sW   : 151552  (2 x 24576 double buffer)
//   bias : 200704  (9216)
//   Wl   : 209920  (3072)
//   bl   : 212992  (16)
//   sLog : 213008  (1536)
//   mbar : 214544  (full[2] @ +0,+8 ; empty[2] @ +16,+24)
#define LDA       296
#define EDGE_SMEM 214592

__global__ __launch_bounds__(544, 1)
void edge_mma_kernel(const int* __restrict__ eidx, const float* __restrict__ eattr,
                     const float* __restrict__ b0, const float* __restrict__ bm,
                     const float* __restrict__ Wl, const float* __restrict__ bl,
                     float* __restrict__ out, int E)
{
    unsigned char* smem = dynsmem;
    __nv_bfloat16* sAh = (__nv_bfloat16*)smem;
    __nv_bfloat16* sAl = (__nv_bfloat16*)(smem + 75776);
    const uint32_t sWu  = smem_u32(smem + 151552);
    float* fBias = (float*)(smem + 200704);
    float* fWl   = (float*)(smem + 209920);
    float* fBl   = (float*)(smem + 212992);
    float* sLog  = (float*)(smem + 213008);
    float* sHidF = (float*)smem;                     // overlays A after layer 8
    const uint32_t mFull  = smem_u32(smem + 214544);
    const uint32_t mEmpty = mFull + 16;

    const int tid = threadIdx.x;
    const int e0  = blockIdx.x * 128;

    if (tid == 0) {
        mbar_init(mFull + 0, 1);  mbar_init(mFull + 8, 1);
        mbar_init(mEmpty + 0, 512); mbar_init(mEmpty + 8, 512);
    }
    for (int i = tid; i < 256;  i += 544) fBias[i] = b0[i];
    for (int i = tid; i < 2048; i += 544) fBias[256 + i] = bm[i];
    for (int i = tid; i < 768;  i += 544) fWl[i] = Wl[i];
    if (tid < 3) fBl[tid] = bl[tid];
    __syncthreads();

    if (tid >= 512) {
        // ------------- producer (only thread 512 acts) ------------------------
        if (tid == 512) {
            uint64_t gB = (uint64_t)__cvta_generic_to_global(g_Bimg);
            for (int c = 0; c < 145; c++) {
                int buf = c & 1;
                if (c >= 2) mbar_wait(mEmpty + buf * 8, ((c >> 1) - 1) & 1);
                mbar_expect_tx(mFull + buf * 8, 24576);
                bulk_copy(sWu + buf * 24576, gB + (uint64_t)c * 24576, 24576, mFull + buf * 8);
            }
        }
        return;
    }

    // ---------------- compute warps (512 threads, 16 warps) ------------------
    const int wid = tid >> 5, l = tid & 31;
    const int gid = l >> 2, tig = l & 3;
    const int mBase = (wid & 3) * 32;
    const int nBase = (wid >> 2) * 64;

    // ldmatrix per-lane address components
    const uint32_t sAhU = smem_u32(sAh);
    // A: tiles [m0k0, m8k0, m0k8, m8k8]
    const int rowA = mBase + ((l >> 3) & 1) * 8 + (l & 7);
    const int colA = (l >> 4) * 8;
    const uint32_t aAddr0 = sAhU + (uint32_t)(rowA * LDA + colA) * 2;
    // B: tiles [n0k0, n0k8, n8k0, n8k8] for an nt-pair (16 n-rows)
    const int nB  = ((l >> 4) & 1) * 8 + (l & 7);
    const int kB  = ((l >> 3) & 1) * 8;
    const uint32_t bAddrOff = (uint32_t)(nB * 48 + kB * 2);

    // ---- A fill: ef = [h[row] | h[col] | eattr | pad] -> bf16 hi/lo ----------
    {
        const int is64 = g_is64;
        int eL = tid >> 2, p = tid & 3;
        int ge = e0 + eL; if (ge >= E) ge = E - 1;
        int rn = is64 ? eidx[2 * (size_t)ge]       : eidx[ge];
        int cn = is64 ? eidx[2 * ((size_t)E + ge)] : eidx[E + ge];
        const float* hr = g_hnode + (size_t)rn * D_IN;
        const float* hc = g_hnode + (size_t)cn * D_IN;
        const float* ea = eattr + (size_t)ge * EAF;
        #pragma unroll 4
        for (int kp = 0; kp < 36; kp++) {
            int k = p * 72 + 2 * kp;
            float v0, v1;
            if (k < 128)      { float2 f = *(const float2*)(hr + k);        v0 = f.x; v1 = f.y; }
            else if (k < 256) { float2 f = *(const float2*)(hc + k - 128);  v0 = f.x; v1 = f.y; }
            else if (k < 272) { float2 f = *(const float2*)(ea + k - 256);  v0 = f.x; v1 = f.y; }
            else              { v0 = 0.f; v1 = 0.f; }
            uint32_t lo, hi = bsplit2(v0, v1, lo);
            *(uint32_t*)(sAh + eL * LDA + k) = hi;
            *(uint32_t*)(sAl + eL * LDA + k) = lo;
        }
    }
    asm volatile("bar.sync 1, 512;" ::: "memory");

    float acc[2][8][4];
    #pragma unroll
    for (int mt = 0; mt < 2; mt++)
        #pragma unroll
        for (int nt = 0; nt < 8; nt++)
            #pragma unroll
            for (int q = 0; q < 4; q++) acc[mt][nt][q] = 0.f;

    int c = 0;
    #pragma unroll 1
    for (int layer = 0; layer < 9; layer++) {
        const int nch = (layer == 0) ? 17 : 16;
        #pragma unroll 1
        for (int ch = 0; ch < nch; ch++, c++) {
            const int buf = c & 1;
            const uint32_t wb = sWu + buf * 24576;
            const int kl = ch * 16;
            // A fragments first (independent of weight buffer)
            uint32_t ah[2][4], al[2][4];
            #pragma unroll
            for (int mt = 0; mt < 2; mt++) {
                uint32_t aa = aAddr0 + (uint32_t)(mt * 16 * LDA + kl) * 2;
                LDM4(ah[mt], aa);
                LDM4(al[mt], aa + 75776);
            }
            mbar_wait(mFull + buf * 8, (c >> 1) & 1);
            // first half: nt pairs 0,1
            #pragma unroll
            for (int ntp = 0; ntp < 2; ntp++) {
                uint32_t ba = wb + (uint32_t)(nBase + ntp * 16) * 48 + bAddrOff;
                uint32_t bh[4], blo[4];
                LDM4(bh, ba);
                LDM4(blo, ba + 12288);
                #pragma unroll
                for (int mt = 0; mt < 2; mt++) {
                    mma16816(acc[mt][2*ntp],   al[mt], bh);
                    mma16816(acc[mt][2*ntp],   ah[mt], blo);
                    mma16816(acc[mt][2*ntp],   ah[mt], bh);
                    mma16816(acc[mt][2*ntp+1], al[mt], bh + 2);
                    mma16816(acc[mt][2*ntp+1], ah[mt], blo + 2);
                    mma16816(acc[mt][2*ntp+1], ah[mt], bh + 2);
                }
            }
            // second half: load both pairs, release buffer, then MMA
            uint32_t bh2[4], blo2[4], bh3[4], blo3[4];
            {
                uint32_t ba2 = wb + (uint32_t)(nBase + 32) * 48 + bAddrOff;
                uint32_t ba3 = wb + (uint32_t)(nBase + 48) * 48 + bAddrOff;
                LDM4(bh2, ba2);  LDM4(blo2, ba2 + 12288);
                LDM4(bh3, ba3);  LDM4(blo3, ba3 + 12288);
            }
            mbar_arrive(mEmpty + buf * 8);
            #pragma unroll
            for (int mt = 0; mt < 2; mt++) {
                mma16816(acc[mt][4], al[mt], bh2);
                mma16816(acc[mt][4], ah[mt], blo2);
                mma16816(acc[mt][4], ah[mt], bh2);
                mma16816(acc[mt][5], al[mt], bh2 + 2);
                mma16816(acc[mt][5], ah[mt], blo2 + 2);
                mma16816(acc[mt][5], ah[mt], bh2 + 2);
                mma16816(acc[mt][6], al[mt], bh3);
                mma16816(acc[mt][6], ah[mt], blo3);
                mma16816(acc[mt][6], ah[mt], bh3);
                mma16816(acc[mt][7], al[mt], bh3 + 2);
                mma16816(acc[mt][7], ah[mt], blo3 + 2);
                mma16816(acc[mt][7], ah[mt], bh3 + 2);
            }
        }

        // ---- epilogue: bias + leaky ----
        const float* bias = fBias + layer * 256;
        #pragma unroll
        for (int nt = 0; nt < 8; nt++) {
            float2 bv = *(const float2*)(bias + nBase + nt * 8 + tig * 2);
            #pragma unroll
            for (int mt = 0; mt < 2; mt++) {
                acc[mt][nt][0] = lrelu(acc[mt][nt][0] + bv.x);
                acc[mt][nt][1] = lrelu(acc[mt][nt][1] + bv.y);
                acc[mt][nt][2] = lrelu(acc[mt][nt][2] + bv.x);
                acc[mt][nt][3] = lrelu(acc[mt][nt][3] + bv.y);
            }
        }
        asm volatile("bar.sync 1, 512;" ::: "memory");  // all reads of A done
        if (layer < 8) {
            #pragma unroll
            for (int mt = 0; mt < 2; mt++)
                #pragma unroll
                for (int nt = 0; nt < 8; nt++) {
                    int r  = mBase + mt * 16 + gid;
                    int cc = nBase + nt * 8 + tig * 2;
                    uint32_t lo0, hi0 = bsplit2(acc[mt][nt][0], acc[mt][nt][1], lo0);
                    uint32_t lo1, hi1 = bsplit2(acc[mt][nt][2], acc[mt][nt][3], lo1);
                    *(uint32_t*)(sAh + r * LDA + cc)       = hi0;
                    *(uint32_t*)(sAl + r * LDA + cc)       = lo0;
                    *(uint32_t*)(sAh + (r + 8) * LDA + cc) = hi1;
                    *(uint32_t*)(sAl + (r + 8) * LDA + cc) = lo1;
                    acc[mt][nt][0] = 0.f; acc[mt][nt][1] = 0.f;
                    acc[mt][nt][2] = 0.f; acc[mt][nt][3] = 0.f;
                }
        } else {
            // final hidden -> fp32 SMEM (overlays A; safe after bar)
            #pragma unroll
            for (int mt = 0; mt < 2; mt++)
                #pragma unroll
                for (int nt = 0; nt < 8; nt++) {
                    int r  = mBase + mt * 16 + gid;
                    int cc = nBase + nt * 8 + tig * 2;
                    *(float2*)(sHidF + r * 260 + cc)       = make_float2(acc[mt][nt][0], acc[mt][nt][1]);
                    *(float2*)(sHidF + (r + 8) * 260 + cc) = make_float2(acc[mt][nt][2], acc[mt][nt][3]);
                }
        }
        asm volatile("bar.sync 1, 512;" ::: "memory");
    }

    // ---- last layer: logits + log_softmax ----
    if (tid < 384) {
        int e = tid / 3, cc = tid - 3 * (tid / 3);
        float a = fBl[cc];
        const float* hrow = sHidF + e * 260;
        #pragma unroll 8
        for (int k = 0; k < HID; k++)
            a = fmaf(hrow[k], fWl[k * 3 + cc], a);
        sLog[e * 3 + cc] = a;
    }
    asm volatile("bar.sync 1, 512;" ::: "memory");
    if (tid < 128) {
        int ge = e0 + tid;
        if (ge < E) {
            float l0 = sLog[tid * 3], l1 = sLog[tid * 3 + 1], l2 = sLog[tid * 3 + 2];
            float m = fmaxf(l0, fmaxf(l1, l2));
            float lse = m + logf(expf(l0 - m) + expf(l1 - m) + expf(l2 - m));
            out[(size_t)ge * 3 + 0] = l0 - lse;
            out[(size_t)ge * 3 + 1] = l1 - lse;
            out[(size_t)ge * 3 + 2] = l2 - lse;
        }
    }
}

// ---------------- launch -----------------------------------------------------
extern "C" void kernel_launch(void* const* d_in, const int* in_sizes, int n_in,
                              void* d_out, int out_size)
{
    const float* x  = (const float*)d_in[0];
    const int*   ei = (const int*)d_in[1];
    const float* ea = (const float*)d_in[2];
    const float* Wx = (const float*)d_in[3];
    const float* bx = (const float*)d_in[4];
    const float* W0 = (const float*)d_in[5];
    const float* b0 = (const float*)d_in[6];
    const float* Wm = (const float*)d_in[7];
    const float* bm = (const float*)d_in[8];
    const float* Wl = (const float*)d_in[9];
    const float* bl = (const float*)d_in[10];
    float* out = (float*)d_out;

    const int N = in_sizes[0] / D_NODE;
    const int E = in_sizes[2] / EAF;

    cudaFuncSetAttribute(node_mlp_kernel, cudaFuncAttributeMaxDynamicSharedMemorySize, NODE_SMEM);
    cudaFuncSetAttribute(edge_mma_kernel, cudaFuncAttributeMaxDynamicSharedMemorySize, EDGE_SMEM);

    detect_idx64_kernel<<<1, 32>>>(ei);
    prep_w_kernel<<<145 * 256, 8>>>(W0, Wm);
    node_mlp_kernel<<<(N + 63) / 64, 256, NODE_SMEM>>>(x, Wx, bx, N);
    edge_mma_kernel<<<(E + 127) / 128, 544, EDGE_SMEM>>>(ei, ea, b0, bm, Wl, bl, out, E);
}

// round 13
// speedup vs baseline: 1.1372x; 1.1372x over previous
#include <cuda_runtime.h>
#include <cuda_bf16.h>
#include <math.h>
#include <stdint.h>

#define D_NODE 256
#define D_IN   128
#define HID    256
#define EAF    16
#define MAXN   65536

// single dynamic-shared declaration for all kernels
extern __shared__ unsigned char dynsmem[];

// ---------------- device globals (no cudaMalloc allowed) --------------------
__device__ float g_hnode[(size_t)MAXN * D_IN];                  // 32 MB
// 145 weight chunk images (k=16 each): [hi 256x16 halves][lo 256x16 halves] = 16384 B
__device__ __align__(128) unsigned char g_Bimg[145 * 16384];    // ~2.3 MB
__device__ int g_is64;

// ---------------- helpers ----------------------------------------------------
__device__ __forceinline__ float lrelu(float v) { return v >= 0.f ? v : 0.01f * v; }
__device__ __forceinline__ unsigned long long pack2(float a) {
    unsigned long long r; asm("mov.b64 %0, {%1, %1};" : "=l"(r) : "f"(a)); return r;
}
__device__ __forceinline__ void fma2(unsigned long long& d,
                                     unsigned long long a, unsigned long long b) {
    asm("fma.rn.f32x2 %0, %1, %2, %0;" : "+l"(d) : "l"(a), "l"(b));
}
__device__ __forceinline__ float2 unpack2(unsigned long long v) {
    float2 r; asm("mov.b64 {%0, %1}, %2;" : "=f"(r.x), "=f"(r.y) : "l"(v)); return r;
}
__device__ __forceinline__ uint32_t smem_u32(const void* p) {
    uint32_t a; asm("{ .reg .u64 t; cvta.to.shared.u64 t, %1; cvt.u32.u64 %0, t; }" : "=r"(a) : "l"(p));
    return a;
}
__device__ __forceinline__ void mbar_init(uint32_t a, uint32_t cnt) {
    asm volatile("mbarrier.init.shared.b64 [%0], %1;" :: "r"(a), "r"(cnt) : "memory");
}
__device__ __forceinline__ void mbar_arrive(uint32_t a) {
    asm volatile("mbarrier.arrive.shared.b64 _, [%0];" :: "r"(a) : "memory");
}
__device__ __forceinline__ void mbar_expect_tx(uint32_t a, uint32_t tx) {
    asm volatile("mbarrier.arrive.expect_tx.shared.b64 _, [%0], %1;" :: "r"(a), "r"(tx) : "memory");
}
__device__ __forceinline__ void mbar_wait(uint32_t a, uint32_t parity) {
    asm volatile("{\n\t.reg .pred P;\n\tLW%=:\n\t"
                 "mbarrier.try_wait.parity.shared::cta.b64 P, [%0], %1, 0x989680;\n\t"
                 "@!P bra LW%=;\n\t}" :: "r"(a), "r"(parity) : "memory");
}
__device__ __forceinline__ void bulk_copy(uint32_t dst, uint64_t gsrc, uint32_t bytes, uint32_t mbar) {
    asm volatile("cp.async.bulk.shared::cluster.global.mbarrier::complete_tx::bytes [%0], [%1], %2, [%3];"
                 :: "r"(dst), "l"(gsrc), "r"(bytes), "r"(mbar) : "memory");
}
// bf16 HMMA: D[16x8] += A[16x16] * B[16x8]  (row.col, f32 acc)
__device__ __forceinline__ void mma16816(float* c, const uint32_t* a, const uint32_t* b) {
    asm volatile("mma.sync.aligned.m16n8k16.row.col.f32.bf16.bf16.f32 "
                 "{%0,%1,%2,%3}, {%4,%5,%6,%7}, {%8,%9}, {%0,%1,%2,%3};"
                 : "+f"(c[0]), "+f"(c[1]), "+f"(c[2]), "+f"(c[3])
                 : "r"(a[0]), "r"(a[1]), "r"(a[2]), "r"(a[3]), "r"(b[0]), "r"(b[1]));
}
__device__ __forceinline__ uint32_t bsplit2(float v0, float v1, uint32_t& lo_out) {
    __nv_bfloat16 h0 = __float2bfloat16(v0), h1 = __float2bfloat16(v1);
    float r0 = v0 - __bfloat162float(h0), r1 = v1 - __bfloat162float(h1);
    __nv_bfloat16 l0 = __float2bfloat16(r0), l1 = __float2bfloat16(r1);
    lo_out = (uint32_t)__bfloat16_as_ushort(l0) | ((uint32_t)__bfloat16_as_ushort(l1) << 16);
    return (uint32_t)__bfloat16_as_ushort(h0) | ((uint32_t)__bfloat16_as_ushort(h1) << 16);
}

// ---------------- index dtype detection -------------------------------------
__global__ void detect_idx64_kernel(const int* __restrict__ ei) {
    if (threadIdx.x == 0) {
        int allzero = 1;
        for (int i = 1; i < 256; i += 2)
            if (ei[i] != 0) { allzero = 0; break; }
        g_is64 = allzero;
    }
}

// ---------------- weight prep -------------------------------------------------
// 145 chunks of k=16: chunks 0..16 -> W0 (K=272 = 17*16, exact);
// chunks 17..144 -> W_mid layer l=(c-17)/16, k-block ((c-17)%16)*16.
// Image: W^T halves at [n][k_local], row stride 16 halves (32 B); lo at +8192.
__global__ void prep_w_kernel(const float* __restrict__ W0, const float* __restrict__ Wm) {
    int b = blockIdx.x;            // 145 * 256 blocks
    int chunk = b >> 8;
    int n     = b & 255;
    int t     = threadIdx.x;       // 8 threads, one k-pair each
    int k0 = 2 * t;
    float w0, w1;
    if (chunk < 17) {
        int kg = chunk * 16 + k0;
        w0 = W0[(size_t)kg       * HID + n];
        w1 = W0[(size_t)(kg + 1) * HID + n];
    } else {
        int l = (chunk - 17) >> 4, kg = ((chunk - 17) & 15) * 16 + k0;
        const float* W = Wm + (size_t)l * HID * HID + (size_t)kg * HID + n;
        w0 = W[0]; w1 = W[HID];
    }
    uint32_t lo, hi = bsplit2(w0, w1, lo);
    unsigned char* img = g_Bimg + (size_t)chunk * 16384;
    *(uint32_t*)(img + n * 32 + k0 * 2)        = hi;
    *(uint32_t*)(img + 8192 + n * 32 + k0 * 2) = lo;
}

// ---------------- node MLP (fp32 FFMA2, proven) ------------------------------
#define NODE_SMEM ((64 * 260 + 16 * 128) * 4)
__global__ __launch_bounds__(256, 1)
void node_mlp_kernel(const float* __restrict__ x, const float* __restrict__ Wx,
                     const float* __restrict__ bx, int N)
{
    float* smem = (float*)dynsmem;
    float* sX = smem;
    float* sW = smem + 64 * 260;
    const int tid = threadIdx.x;
    const int tx = tid & 15, ty = tid >> 4;
    const int m0 = blockIdx.x * 64;
    {
        int e = tid >> 2, p = tid & 3;
        int r = m0 + e; if (r >= N) r = N - 1;
        const float4* src = (const float4*)(x + (size_t)r * D_NODE) + p * 16;
        float4* dst = (float4*)(sX + e * 260) + p * 16;
        #pragma unroll
        for (int j = 0; j < 16; j++) dst[j] = src[j];
    }
    const int krow = tid >> 4, seg = tid & 15;
    const float4* gsrc = (const float4*)(Wx + krow * D_IN + seg * 8);
    float4 p0 = gsrc[0], p1 = gsrc[1];
    unsigned long long acc[4][4];
    #pragma unroll
    for (int i = 0; i < 4; i++)
        #pragma unroll
        for (int j = 0; j < 4; j++) acc[i][j] = 0ull;
    const float* aBase = sX + (ty * 4) * 260;
    #pragma unroll 1
    for (int c = 0; c < 16; c++) {
        __syncthreads();
        float4* wd = (float4*)(sW + krow * D_IN + seg * 8);
        wd[0] = p0; wd[1] = p1;
        __syncthreads();
        if (c < 15) { const float4* g2 = gsrc + (size_t)(c + 1) * 512; p0 = g2[0]; p1 = g2[1]; }
        const float* aP = aBase + c * 16;
        #pragma unroll
        for (int kk = 0; kk < 16; kk++) {
            unsigned long long a0 = pack2(aP[kk]);
            unsigned long long a1 = pack2(aP[260 + kk]);
            unsigned long long a2 = pack2(aP[520 + kk]);
            unsigned long long a3 = pack2(aP[780 + kk]);
            const float* wrow = sW + kk * D_IN + tx * 4;
            #pragma unroll
            for (int g = 0; g < 2; g++) {
                ulonglong2 w = *(const ulonglong2*)(wrow + g * 64);
                fma2(acc[0][2*g], a0, w.x); fma2(acc[0][2*g+1], a0, w.y);
                fma2(acc[1][2*g], a1, w.x); fma2(acc[1][2*g+1], a1, w.y);
                fma2(acc[2][2*g], a2, w.x); fma2(acc[2][2*g+1], a2, w.y);
                fma2(acc[3][2*g], a3, w.x); fma2(acc[3][2*g+1], a3, w.y);
            }
        }
    }
    #pragma unroll
    for (int g = 0; g < 2; g++) {
        float4 bias = *(const float4*)(bx + tx * 4 + g * 64);
        #pragma unroll
        for (int i = 0; i < 4; i++) {
            int r = m0 + ty * 4 + i;
            if (r < N) {
                float2 u0 = unpack2(acc[i][2*g]);
                float2 u1 = unpack2(acc[i][2*g+1]);
                float4 v = make_float4(lrelu(u0.x + bias.x), lrelu(u0.y + bias.y),
                                       lrelu(u1.x + bias.z), lrelu(u1.y + bias.w));
                *(float4*)(g_hnode + (size_t)r * D_IN + tx * 4 + g * 64) = v;
            }
        }
    }
}

// ---------------- fused mma.sync edge pipeline (M=64, 2 CTAs/SM) --------------
// SMEM layout (bytes):
//   sAh  : 0       (64 x 296 halves = 37888)
//   sAl  : 37888   (37888)                    -> end 75776
//   sW   : 75776   (2 x 16384 double buffer)  -> end 108544
//   sLog : 108544  (64 x 3 x 4 = 768)         -> end 109312
//   mbar : 109312  (full[2] @ +0,+8 ; empty[2] @ +16,+24)
// total 109344 -> 109440 (pad). Two CTAs: 218.9 KB <= 228 KB.
#define LDA       296
#define EDGE_SMEM 109440

__global__ __launch_bounds__(288, 2)
void edge_mma_kernel(const int* __restrict__ eidx, const float* __restrict__ eattr,
                     const float* __restrict__ b0, const float* __restrict__ bm,
                     const float* __restrict__ Wl, const float* __restrict__ bl,
                     float* __restrict__ out, int E)
{
    unsigned char* smem = dynsmem;
    __nv_bfloat16* sAh = (__nv_bfloat16*)smem;
    __nv_bfloat16* sAl = (__nv_bfloat16*)(smem + 37888);
    const uint32_t sWu  = smem_u32(smem + 75776);
    float* sLog  = (float*)(smem + 108544);
    float* sHidF = (float*)smem;                     // overlays A after layer 8
    const uint32_t mFull  = smem_u32(smem + 109312);
    const uint32_t mEmpty = mFull + 16;

    const int tid = threadIdx.x;
    const int e0  = blockIdx.x * 64;

    if (tid == 0) {
        mbar_init(mFull + 0, 1);  mbar_init(mFull + 8, 1);
        mbar_init(mEmpty + 0, 256); mbar_init(mEmpty + 8, 256);
    }
    __syncthreads();

    if (tid >= 256) {
        // ------------- producer (only thread 256 acts) ------------------------
        if (tid == 256) {
            uint64_t gB = (uint64_t)__cvta_generic_to_global(g_Bimg);
            for (int c = 0; c < 145; c++) {
                int buf = c & 1;
                if (c >= 2) mbar_wait(mEmpty + buf * 8, ((c >> 1) - 1) & 1);
                mbar_expect_tx(mFull + buf * 8, 16384);
                bulk_copy(sWu + buf * 16384, gB + (uint64_t)c * 16384, 16384, mFull + buf * 8);
            }
        }
        return;
    }

    // ---------------- compute warps (256 threads, 8 warps) -------------------
    const int wid = tid >> 5, l = tid & 31;
    const int gid = l >> 2, tig = l & 3;
    const int mBase = (wid & 1) * 32;
    const int nBase = (wid >> 1) * 64;

    // ---- A fill: ef = [h[row] | h[col] | eattr | pad] -> bf16 hi/lo ----------
    {
        const int is64 = g_is64;
        int eL = tid >> 2, p = tid & 3;
        int ge = e0 + eL; if (ge >= E) ge = E - 1;
        int rn = is64 ? eidx[2 * (size_t)ge]       : eidx[ge];
        int cn = is64 ? eidx[2 * ((size_t)E + ge)] : eidx[E + ge];
        const float* hr = g_hnode + (size_t)rn * D_IN;
        const float* hc = g_hnode + (size_t)cn * D_IN;
        const float* ea = eattr + (size_t)ge * EAF;
        #pragma unroll 4
        for (int kp = 0; kp < 36; kp++) {
            int k = p * 72 + 2 * kp;
            float v0, v1;
            if (k < 128)      { float2 f = *(const float2*)(hr + k);        v0 = f.x; v1 = f.y; }
            else if (k < 256) { float2 f = *(const float2*)(hc + k - 128);  v0 = f.x; v1 = f.y; }
            else if (k < 272) { float2 f = *(const float2*)(ea + k - 256);  v0 = f.x; v1 = f.y; }
            else              { v0 = 0.f; v1 = 0.f; }
            uint32_t lo, hi = bsplit2(v0, v1, lo);
            *(uint32_t*)(sAh + eL * LDA + k) = hi;
            *(uint32_t*)(sAl + eL * LDA + k) = lo;
        }
    }
    asm volatile("bar.sync 1, 256;" ::: "memory");

    float acc[2][8][4];
    #pragma unroll
    for (int mt = 0; mt < 2; mt++)
        #pragma unroll
        for (int nt = 0; nt < 8; nt++)
            #pragma unroll
            for (int q = 0; q < 4; q++) acc[mt][nt][q] = 0.f;

    int c = 0;
    #pragma unroll 1
    for (int layer = 0; layer < 9; layer++) {
        const int nch = (layer == 0) ? 17 : 16;
        #pragma unroll 1
        for (int ch = 0; ch < nch; ch++, c++) {
            const int buf = c & 1;
            const uint32_t wb = sWu + buf * 16384;
            mbar_wait(mFull + buf * 8, (c >> 1) & 1);
            const int kl = ch * 16;
            uint32_t ah[2][4], al[2][4];
            #pragma unroll
            for (int mt = 0; mt < 2; mt++) {
                int r0 = mBase + mt * 16 + gid;
                int cb = kl + tig * 2;
                ah[mt][0] = *(const uint32_t*)(sAh + r0 * LDA + cb);
                ah[mt][1] = *(const uint32_t*)(sAh + (r0 + 8) * LDA + cb);
                ah[mt][2] = *(const uint32_t*)(sAh + r0 * LDA + cb + 8);
                ah[mt][3] = *(const uint32_t*)(sAh + (r0 + 8) * LDA + cb + 8);
                al[mt][0] = *(const uint32_t*)(sAl + r0 * LDA + cb);
                al[mt][1] = *(const uint32_t*)(sAl + (r0 + 8) * LDA + cb);
                al[mt][2] = *(const uint32_t*)(sAl + r0 * LDA + cb + 8);
                al[mt][3] = *(const uint32_t*)(sAl + (r0 + 8) * LDA + cb + 8);
            }
            #pragma unroll
            for (int nt = 0; nt < 8; nt++) {
                int n = nBase + nt * 8 + gid;
                uint32_t a0 = wb + n * 32 + tig * 4;
                uint32_t bh[2], blo[2];
                asm volatile("ld.shared.b32 %0, [%2]; ld.shared.b32 %1, [%2+16];"
                             : "=r"(bh[0]), "=r"(bh[1]) : "r"(a0));
                asm volatile("ld.shared.b32 %0, [%2+8192]; ld.shared.b32 %1, [%2+8208];"
                             : "=r"(blo[0]), "=r"(blo[1]) : "r"(a0));
                #pragma unroll
                for (int mt = 0; mt < 2; mt++) {
                    mma16816(acc[mt][nt], al[mt], bh);
                    mma16816(acc[mt][nt], ah[mt], blo);
                    mma16816(acc[mt][nt], ah[mt], bh);
                }
            }
            mbar_arrive(mEmpty + buf * 8);
        }

        // ---- epilogue: bias (L2-hot LDG) + leaky ----
        const float* bias = (layer == 0) ? b0 : (bm + (size_t)(layer - 1) * 256);
        float2 bv[8];
        #pragma unroll
        for (int nt = 0; nt < 8; nt++)
            bv[nt] = __ldg((const float2*)(bias + nBase + nt * 8 + tig * 2));
        #pragma unroll
        for (int nt = 0; nt < 8; nt++) {
            #pragma unroll
            for (int mt = 0; mt < 2; mt++) {
                acc[mt][nt][0] = lrelu(acc[mt][nt][0] + bv[nt].x);
                acc[mt][nt][1] = lrelu(acc[mt][nt][1] + bv[nt].y);
                acc[mt][nt][2] = lrelu(acc[mt][nt][2] + bv[nt].x);
                acc[mt][nt][3] = lrelu(acc[mt][nt][3] + bv[nt].y);
            }
        }
        asm volatile("bar.sync 1, 256;" ::: "memory");  // all reads of A done
        if (layer < 8) {
            #pragma unroll
            for (int mt = 0; mt < 2; mt++)
                #pragma unroll
                for (int nt = 0; nt < 8; nt++) {
                    int r  = mBase + mt * 16 + gid;
                    int cc = nBase + nt * 8 + tig * 2;
                    uint32_t lo0, hi0 = bsplit2(acc[mt][nt][0], acc[mt][nt][1], lo0);
                    uint32_t lo1, hi1 = bsplit2(acc[mt][nt][2], acc[mt][nt][3], lo1);
                    *(uint32_t*)(sAh + r * LDA + cc)       = hi0;
                    *(uint32_t*)(sAl + r * LDA + cc)       = lo0;
                    *(uint32_t*)(sAh + (r + 8) * LDA + cc) = hi1;
                    *(uint32_t*)(sAl + (r + 8) * LDA + cc) = lo1;
                    acc[mt][nt][0] = 0.f; acc[mt][nt][1] = 0.f;
                    acc[mt][nt][2] = 0.f; acc[mt][nt][3] = 0.f;
                }
        } else {
            // final hidden -> fp32 SMEM (overlays A; safe after bar)
            #pragma unroll
            for (int mt = 0; mt < 2; mt++)
                #pragma unroll
                for (int nt = 0; nt < 8; nt++) {
                    int r  = mBase + mt * 16 + gid;
                    int cc = nBase + nt * 8 + tig * 2;
                    *(float2*)(sHidF + r * 260 + cc)       = make_float2(acc[mt][nt][0], acc[mt][nt][1]);
                    *(float2*)(sHidF + (r + 8) * 260 + cc) = make_float2(acc[mt][nt][2], acc[mt][nt][3]);
                }
        }
        asm volatile("bar.sync 1, 256;" ::: "memory");
    }

    // ---- last layer: logits + log_softmax ----
    if (tid < 192) {
        int e = tid / 3, cc = tid - 3 * (tid / 3);
        float a = __ldg(bl + cc);
        const float* hrow = sHidF + e * 260;
        #pragma unroll 8
        for (int k = 0; k < HID; k++)
            a = fmaf(hrow[k], __ldg(Wl + k * 3 + cc), a);
        sLog[e * 3 + cc] = a;
    }
    asm volatile("bar.sync 1, 256;" ::: "memory");
    if (tid < 64) {
        int ge = e0 + tid;
        if (ge < E) {
            float l0 = sLog[tid * 3], l1 = sLog[tid * 3 + 1], l2 = sLog[tid * 3 + 2];
            float m = fmaxf(l0, fmaxf(l1, l2));
            float lse = m + logf(expf(l0 - m) + expf(l1 - m) + expf(l2 - m));
            out[(size_t)ge * 3 + 0] = l0 - lse;
            out[(size_t)ge * 3 + 1] = l1 - lse;
            out[(size_t)ge * 3 + 2] = l2 - lse;
        }
    }
}

// ---------------- launch -----------------------------------------------------
extern "C" void kernel_launch(void* const* d_in, const int* in_sizes, int n_in,
                              void* d_out, int out_size)
{
    const float* x  = (const float*)d_in[0];
    const int*   ei = (const int*)d_in[1];
    const float* ea = (const float*)d_in[2];
    const float* Wx = (const float*)d_in[3];
    const float* bx = (const float*)d_in[4];
    const float* W0 = (const float*)d_in[5];
    const float* b0 = (const float*)d_in[6];
    const float* Wm = (const float*)d_in[7];
    const float* bm = (const float*)d_in[8];
    const float* Wl = (const float*)d_in[9];
    const float* bl = (const float*)d_in[10];
    float* out = (float*)d_out;

    const int N = in_sizes[0] / D_NODE;
    const int E = in_sizes[2] / EAF;

    cudaFuncSetAttribute(node_mlp_kernel, cudaFuncAttributeMaxDynamicSharedMemorySize, NODE_SMEM);
    cudaFuncSetAttribute(edge_mma_kernel, cudaFuncAttributeMaxDynamicSharedMemorySize, EDGE_SMEM);

    detect_idx64_kernel<<<1, 32>>>(ei);
    prep_w_kernel<<<145 * 256, 8>>>(W0, Wm);
    node_mlp_kernel<<<(N + 63) / 64, 256, NODE_SMEM>>>(x, Wx, bx, N);
    edge_mma_kernel<<<(E + 63) / 64, 288, EDGE_SMEM>>>(ei, ea, b0, bm, Wl, bl, out, E);
}